// round 9
// baseline (speedup 1.0000x reference)
#include <cuda_runtime.h>
#include <cuda_bf16.h>
#include <cstdint>
#include <cstddef>

#define Bq 8
#define Nq 2048
#define Kq 32
#define Fq 256          // F_IN = F_OUT
#define Cq 512          // 2*F_OUT
#define Mq (Bq*Nq)      // 16384 rows

typedef unsigned int u32;
typedef unsigned long long u64;

// Scratch (no cudaMalloc allowed)
__device__ __nv_bfloat16 g_ah[(size_t)Mq * Fq];   // x hi
__device__ __nv_bfloat16 g_al[(size_t)Mq * Fq];   // x lo
__device__ __nv_bfloat16 g_anh[(size_t)Mq * Fq];  // xn hi
__device__ __nv_bfloat16 g_anl[(size_t)Mq * Fq];  // xn lo
__device__ __nv_bfloat16 g_bh[(size_t)Cq * Fq];   // [Wx;Wn] hi, rows=channel
__device__ __nv_bfloat16 g_bl[(size_t)Cq * Fq];   // [Wx;Wn] lo
__device__ float g_sum[Cq];
__device__ float g_sumsq[Cq];

// ---------------------------------------------------------------------------
// helpers
// ---------------------------------------------------------------------------
__device__ __forceinline__ u32 s2u(const void* p) {
    return (u32)__cvta_generic_to_shared(p);
}
__device__ __forceinline__ void cp16(u32 d, const void* g) {
    asm volatile("cp.async.cg.shared.global [%0], [%1], 16;" :: "r"(d), "l"(g));
}
__device__ __forceinline__ void ldmx4(u32* r, u32 a) {
    asm volatile("ldmatrix.sync.aligned.m8n8.x4.shared.b16 {%0,%1,%2,%3}, [%4];"
                 : "=r"(r[0]), "=r"(r[1]), "=r"(r[2]), "=r"(r[3]) : "r"(a));
}
__device__ __forceinline__ void ldmx2(u32* r, u32 a) {
    asm volatile("ldmatrix.sync.aligned.m8n8.x2.shared.b16 {%0,%1}, [%2];"
                 : "=r"(r[0]), "=r"(r[1]) : "r"(a));
}
__device__ __forceinline__ void mma16816(float* d, const u32* a, const u32* b) {
    asm volatile(
        "mma.sync.aligned.m16n8k16.row.col.f32.bf16.bf16.f32 "
        "{%0,%1,%2,%3}, {%4,%5,%6,%7}, {%8,%9}, {%0,%1,%2,%3};"
        : "+f"(d[0]), "+f"(d[1]), "+f"(d[2]), "+f"(d[3])
        : "r"(a[0]), "r"(a[1]), "r"(a[2]), "r"(a[3]), "r"(b[0]), "r"(b[1]));
}
__device__ __forceinline__ uint2 pack4(float a, float b, float c, float d) {
    __nv_bfloat162 lo = __floats2bfloat162_rn(a, b);
    __nv_bfloat162 hi = __floats2bfloat162_rn(c, d);
    uint2 r;
    r.x = *reinterpret_cast<u32*>(&lo);
    r.y = *reinterpret_cast<u32*>(&hi);
    return r;
}

// ---------------------------------------------------------------------------
// Kernel 1: gather+mean, hi/lo bf16 split of x and xn; weight pack (blocks<512);
// block 0 zeroes BN stat accumulators.
// ---------------------------------------------------------------------------
__global__ __launch_bounds__(256) void k_gather(const float4* __restrict__ x4,
                                                const int* __restrict__ idx,
                                                const float* __restrict__ Wx,
                                                const float* __restrict__ Wn) {
    const int tid = threadIdx.x;
    if (blockIdx.x == 0) {
        g_sum[tid] = 0.f;   g_sum[tid + 256] = 0.f;
        g_sumsq[tid] = 0.f; g_sumsq[tid + 256] = 0.f;
    }
    if (blockIdx.x < Cq) {    // weight pack: channel = blockIdx, k = tid
        const int c = blockIdx.x;
        float wv = (c < 256) ? Wx[c * Fq + tid] : Wn[(c - 256) * Fq + tid];
        __nv_bfloat16 h = __float2bfloat16(wv);
        g_bh[c * Fq + tid] = h;
        g_bl[c * Fq + tid] = __float2bfloat16(wv - __bfloat162float(h));
    }
    __shared__ int nbr[4][Kq];
    const int rr = tid >> 6;
    const int q  = tid & 63;
    const int r  = blockIdx.x * 4 + rr;
    const int b  = r >> 11;
    const int n  = r & (Nq - 1);

    if (tid < 128) {
        int k   = tid & 31;
        int rr2 = tid >> 5;
        int n2  = (blockIdx.x * 4 + rr2) & (Nq - 1);
        nbr[rr2][k] = idx[n2 * Kq + k];
    }
    __syncthreads();

    const float4* xb = x4 + (size_t)b * Nq * (Fq / 4);
    float4 acc = make_float4(0.f, 0.f, 0.f, 0.f);
#pragma unroll
    for (int k = 0; k < Kq; k++) {
        float4 v = xb[(size_t)nbr[rr][k] * (Fq / 4) + q];
        acc.x += v.x; acc.y += v.y; acc.z += v.z; acc.w += v.w;
    }
    const float s = 1.f / 32.f;
    acc.x *= s; acc.y *= s; acc.z *= s; acc.w *= s;
    const float4 xv = xb[(size_t)n * (Fq / 4) + q];

    const size_t o = (size_t)r * Fq + 4 * q;
    float h0, h1, h2, h3;
    h0 = __bfloat162float(__float2bfloat16(xv.x));
    h1 = __bfloat162float(__float2bfloat16(xv.y));
    h2 = __bfloat162float(__float2bfloat16(xv.z));
    h3 = __bfloat162float(__float2bfloat16(xv.w));
    *(uint2*)(g_ah + o) = pack4(h0, h1, h2, h3);
    *(uint2*)(g_al + o) = pack4(xv.x - h0, xv.y - h1, xv.z - h2, xv.w - h3);
    h0 = __bfloat162float(__float2bfloat16(acc.x));
    h1 = __bfloat162float(__float2bfloat16(acc.y));
    h2 = __bfloat162float(__float2bfloat16(acc.z));
    h3 = __bfloat162float(__float2bfloat16(acc.w));
    *(uint2*)(g_anh + o) = pack4(h0, h1, h2, h3);
    *(uint2*)(g_anl + o) = pack4(acc.x - h0, acc.y - h1, acc.z - h2, acc.w - h3);
}

// ---------------------------------------------------------------------------
// Kernel 2: mma.sync bf16 dual GEMM, 3-term hi/lo fp32 emulation, fused
// bias / row L2-norm / ReLU / BN-stat epilogue.
// CTA: 64 rows x 512 channels, 512 threads (16 warps).
// Warp w: wr = w&1 (32-row half), wn = w>>1 (64-channel octet).
// wn<4 -> A = x (self channels), wn>=4 -> A = xn (neighbor channels).
// K pipeline: 16 steps of k16, 3-stage 16B cp.async, one barrier per step.
// ---------------------------------------------------------------------------
#define APITCH 48                 // bytes per 16-bf16 row (32B data + pad)
#define AOFF  3072                // per A-array tile bytes (64*48)
#define BOFF  24576               // per B-array tile bytes (512*48)
#define STAGE_SZ (4*AOFF + 2*BOFF)   // 61440
#define NSTG 3
#define SM_TILES 4608             // tiles (and epi staging) start here
#define EPITCH 516                // epilogue staging pitch (floats)
#define SMEMM (SM_TILES + NSTG*STAGE_SZ)   // 188928

__global__ __launch_bounds__(512, 1) void k_mma(const float* __restrict__ bx,
                                                const float* __restrict__ bn,
                                                float* __restrict__ out) {
    extern __shared__ char sm[];
    float* sbias = (float*)sm;            // [512]
    float* ssqp  = (float*)(sm + 2048);   // [64][8]
    float* rinv  = (float*)(sm + 4096);   // [64]

    const int tid  = threadIdx.x;
    const int lane = tid & 31;
    const int w    = tid >> 5;
    const int wr   = w & 1;               // row half (32 rows)
    const int wn   = w >> 1;              // channel octet (64 ch)
    const int row0 = blockIdx.x * 64;

    sbias[tid] = (tid < 256) ? bx[tid] : bn[tid - 256];

    const u32 smt = s2u(sm) + SM_TILES;

    // ---- per-thread cp.async source/dest (hoisted) ----
    // A: 4 arrays x 128 chunks; exactly one chunk per thread.
    const int arrA = tid >> 7;            // 0 xh, 1 xl, 2 nh, 3 nl
    const int ra   = (tid & 127) >> 1;
    const int hfA  = tid & 1;
    const __nv_bfloat16* srcA =
        ((arrA == 0) ? g_ah : (arrA == 1) ? g_al : (arrA == 2) ? g_anh : g_anl)
        + (size_t)(row0 + ra) * Fq + hfA * 8;
    const u32 dstA = (u32)(arrA * AOFF + ra * APITCH + hfA * 16);
    // B: 2 arrays x 1024 chunks; 4 per thread.
    const __nv_bfloat16* srcB[4];
    u32 dstB[4];
#pragma unroll
    for (int i = 0; i < 4; i++) {
        const int b2  = tid + 512 * i;
        const int arr = b2 >> 10;
        const int id2 = b2 & 1023;
        const int c   = id2 >> 1;
        const int hf  = id2 & 1;
        srcB[i] = (arr ? g_bl : g_bh) + (size_t)c * Fq + hf * 8;
        dstB[i] = (u32)(4 * AOFF + arr * BOFF + c * APITCH + hf * 16);
    }

    auto issue = [&](int kt, int st) {
        const u32 sb = smt + st * STAGE_SZ;
        const int ko = kt * 16;
        cp16(sb + dstA, srcA + ko);
#pragma unroll
        for (int i = 0; i < 4; i++)
            cp16(sb + dstB[i], srcB[i] + ko);
        asm volatile("cp.async.commit_group;");
    };

    float acc[2][8][4];
#pragma unroll
    for (int mt = 0; mt < 2; mt++)
#pragma unroll
        for (int tn = 0; tn < 8; tn++)
#pragma unroll
            for (int k = 0; k < 4; k++) acc[mt][tn][k] = 0.f;

    issue(0, 0);
    issue(1, 1);

    const int arow   = (lane & 7) + ((lane >> 3) & 1) * 8;
    const int acol16 = (lane >> 4) * 16;
    const int brow   = lane & 7;
    const int bcol16 = ((lane >> 3) & 1) * 16;
    const u32 aoff   = (wn >= 4) ? (u32)(2 * AOFF) : 0u;

    int st = 0;                 // kt % 3
    int stn = 2;                // (kt+2) % 3
    for (int kt = 0; kt < 16; kt++) {
        if (kt < 15) asm volatile("cp.async.wait_group 1;");
        else         asm volatile("cp.async.wait_group 0;");
        __syncthreads();

        if (kt < 14) issue(kt + 2, stn);

        const u32 sb = smt + st * STAGE_SZ;
        const u32 ab = sb + aoff;
        const u32 bb = sb + 4 * AOFF;

        u32 ahi[2][4], alo[2][4];
#pragma unroll
        for (int mt = 0; mt < 2; mt++) {
            const u32 ad = ab + (wr * 32 + mt * 16 + arow) * APITCH + acol16;
            ldmx4(ahi[mt], ad);
            ldmx4(alo[mt], ad + AOFF);
        }
#pragma unroll
        for (int nc = 0; nc < 2; nc++) {
            u32 bhf[4][2], blf[4][2];
#pragma unroll
            for (int j = 0; j < 4; j++) {
                const int ch = wn * 64 + (nc * 4 + j) * 8;
                const u32 bd = bb + (ch + brow) * APITCH + bcol16;
                ldmx2(bhf[j], bd);
                ldmx2(blf[j], bd + BOFF);
            }
#pragma unroll
            for (int mt = 0; mt < 2; mt++)
#pragma unroll
                for (int j = 0; j < 4; j++) {
                    float* d = acc[mt][nc * 4 + j];
                    mma16816(d, ahi[mt], bhf[j]);
                    mma16816(d, ahi[mt], blf[j]);
                    mma16816(d, alo[mt], bhf[j]);
                }
        }

        st  = (st == 2)  ? 0 : st + 1;
        stn = (stn == 2) ? 0 : stn + 1;
    }
    __syncthreads();

    // ---- Epilogue: stage bias-added accums to smem [64][EPITCH] ----
    float* sg = (float*)(sm + SM_TILES);
#pragma unroll
    for (int mt = 0; mt < 2; mt++) {
        const int re = wr * 32 + mt * 16 + (lane >> 2);
#pragma unroll
        for (int tn = 0; tn < 8; tn++) {
            const int col = wn * 64 + tn * 8 + 2 * (lane & 3);
            const float2 bv = *(float2*)&sbias[col];
            float* p0 = &sg[re * EPITCH + col];
            p0[0] = acc[mt][tn][0] + bv.x;
            p0[1] = acc[mt][tn][1] + bv.y;
            float* p1 = &sg[(re + 8) * EPITCH + col];
            p1[0] = acc[mt][tn][2] + bv.x;
            p1[1] = acc[mt][tn][3] + bv.y;
        }
    }
    __syncthreads();

    // row sum-of-squares: thread -> (row = tid>>3, octet q = tid&7 of 64 ch)
    {
        const int r = tid >> 3, q = tid & 7;
        float s = 0.f;
#pragma unroll
        for (int i = 0; i < 16; i++) {
            const int idx2 = (i + 2 * q) & 15;          // bank stagger
            float4 v = *(const float4*)&sg[r * EPITCH + q * 64 + idx2 * 4];
            s += v.x * v.x + v.y * v.y + v.z * v.z + v.w * v.w;
        }
        ssqp[r * 8 + q] = s;
    }
    __syncthreads();
    if (tid < 64) {
        float s = 0.f;
#pragma unroll
        for (int q = 0; q < 8; q++) s += ssqp[tid * 8 + q];
        rinv[tid] = 1.f / fmaxf(sqrtf(s), 1e-12f);
    }
    __syncthreads();

    // normalize + relu + store + BN stats. c4 = tid&127, row group tid>>7.
    {
        const int c4 = tid & 127;
        const int rg = tid >> 7;                 // 0..3, 16 rows each
        float s0 = 0.f, s1 = 0.f, s2 = 0.f, s3 = 0.f;
        float q0 = 0.f, q1 = 0.f, q2 = 0.f, q3 = 0.f;
#pragma unroll 4
        for (int i = 0; i < 16; i++) {
            const int r = rg * 16 + i;
            float4 v = *(float4*)&sg[r * EPITCH + c4 * 4];
            const float rv = rinv[r];
            v.x = fmaxf(v.x * rv, 0.f); v.y = fmaxf(v.y * rv, 0.f);
            v.z = fmaxf(v.z * rv, 0.f); v.w = fmaxf(v.w * rv, 0.f);
            *(float4*)(out + (size_t)(row0 + r) * Cq + c4 * 4) = v;
            s0 += v.x; s1 += v.y; s2 += v.z; s3 += v.w;
            q0 += v.x * v.x; q1 += v.y * v.y; q2 += v.z * v.z; q3 += v.w * v.w;
        }
        atomicAdd(&g_sum[c4 * 4 + 0], s0);  atomicAdd(&g_sum[c4 * 4 + 1], s1);
        atomicAdd(&g_sum[c4 * 4 + 2], s2);  atomicAdd(&g_sum[c4 * 4 + 3], s3);
        atomicAdd(&g_sumsq[c4 * 4 + 0], q0); atomicAdd(&g_sumsq[c4 * 4 + 1], q1);
        atomicAdd(&g_sumsq[c4 * 4 + 2], q2); atomicAdd(&g_sumsq[c4 * 4 + 3], q3);
    }
}

// ---------------------------------------------------------------------------
// Kernel 3: per-block BN fold (stats -> scale/shift in smem) + apply, 4x ILP.
// ---------------------------------------------------------------------------
#define QUAR ((size_t)Mq * (Cq / 4) / 4)     // float4 count of quarter output
__global__ __launch_bounds__(256) void k_apply(float4* __restrict__ out4,
                                               const float* __restrict__ gamma,
                                               const float* __restrict__ beta) {
    __shared__ float sc[Cq], sh[Cq];
    const int t = threadIdx.x;
    const float inv_n = 1.f / (float)Mq;
#pragma unroll
    for (int o = 0; o < 2; o++) {
        const int c = t + 256 * o;
        float mu  = g_sum[c] * inv_n;
        float var = fmaxf(g_sumsq[c] * inv_n - mu * mu, 0.f);
        float iv  = rsqrtf(var + 1e-5f);
        float s   = gamma[c] * iv;
        sc[c] = s;
        sh[c] = beta[c] - mu * s;
    }
    __syncthreads();
    const size_t i = (size_t)blockIdx.x * 256 + t;
    const int p = (int)(i & 127) * 4;
    const float4 s4 = *(float4*)&sc[p];
    const float4 h4 = *(float4*)&sh[p];
#pragma unroll
    for (int u = 0; u < 4; u++) {
        float4 v = out4[i + u * QUAR];
        v.x = v.x * s4.x + h4.x;  v.y = v.y * s4.y + h4.y;
        v.z = v.z * s4.z + h4.z;  v.w = v.w * s4.w + h4.w;
        out4[i + u * QUAR] = v;
    }
}

// ---------------------------------------------------------------------------
extern "C" void kernel_launch(void* const* d_in, const int* in_sizes, int n_in,
                              void* d_out, int out_size) {
    const float* x     = (const float*)d_in[0];
    const int*   idx   = (const int*)  d_in[1];
    const float* Wx    = (const float*)d_in[2];
    const float* bx    = (const float*)d_in[3];
    const float* Wn    = (const float*)d_in[4];
    const float* bn    = (const float*)d_in[5];
    const float* gamma = (const float*)d_in[6];
    const float* beta  = (const float*)d_in[7];
    float* out = (float*)d_out;

    cudaFuncSetAttribute(k_mma, cudaFuncAttributeMaxDynamicSharedMemorySize,
                         SMEMM);

    k_gather<<<Mq / 4, 256>>>((const float4*)x, idx, Wx, Wn);
    k_mma<<<Mq / 64, 512, SMEMM>>>(bx, bn, out);
    k_apply<<<(int)(QUAR / 256), 256>>>((float4*)out, gamma, beta);
}

// round 12
// speedup vs baseline: 1.6377x; 1.6377x over previous
#include <cuda_runtime.h>
#include <cuda_bf16.h>
#include <cstdint>
#include <cstddef>

#define Bq 8
#define Nq 2048
#define Kq 32
#define Fq 256          // F_IN = F_OUT
#define Cq 512          // 2*F_OUT
#define Mq (Bq*Nq)      // 16384 rows

typedef unsigned int u32;
typedef unsigned long long u64;

// Scratch (no cudaMalloc allowed)
__device__ __nv_bfloat16 g_ah[(size_t)Mq * Fq];   // x hi
__device__ __nv_bfloat16 g_al[(size_t)Mq * Fq];   // x lo
__device__ __nv_bfloat16 g_anh[(size_t)Mq * Fq];  // xn hi
__device__ __nv_bfloat16 g_anl[(size_t)Mq * Fq];  // xn lo
__device__ __nv_bfloat16 g_bh[(size_t)Cq * Fq];   // [Wx;Wn] hi, rows=channel
__device__ __nv_bfloat16 g_bl[(size_t)Cq * Fq];   // [Wx;Wn] lo
__device__ float g_sum[Cq];
__device__ float g_sumsq[Cq];

// ---------------------------------------------------------------------------
// helpers
// ---------------------------------------------------------------------------
__device__ __forceinline__ u32 s2u(const void* p) {
    return (u32)__cvta_generic_to_shared(p);
}
__device__ __forceinline__ void cp16(u32 d, const void* g) {
    asm volatile("cp.async.cg.shared.global [%0], [%1], 16;" :: "r"(d), "l"(g));
}
__device__ __forceinline__ void ldmx4(u32* r, u32 a) {
    asm volatile("ldmatrix.sync.aligned.m8n8.x4.shared.b16 {%0,%1,%2,%3}, [%4];"
                 : "=r"(r[0]), "=r"(r[1]), "=r"(r[2]), "=r"(r[3]) : "r"(a));
}
__device__ __forceinline__ void ldmx2(u32* r, u32 a) {
    asm volatile("ldmatrix.sync.aligned.m8n8.x2.shared.b16 {%0,%1}, [%2];"
                 : "=r"(r[0]), "=r"(r[1]) : "r"(a));
}
__device__ __forceinline__ void mma16816(float* d, const u32* a, const u32* b) {
    asm volatile(
        "mma.sync.aligned.m16n8k16.row.col.f32.bf16.bf16.f32 "
        "{%0,%1,%2,%3}, {%4,%5,%6,%7}, {%8,%9}, {%0,%1,%2,%3};"
        : "+f"(d[0]), "+f"(d[1]), "+f"(d[2]), "+f"(d[3])
        : "r"(a[0]), "r"(a[1]), "r"(a[2]), "r"(a[3]), "r"(b[0]), "r"(b[1]));
}
__device__ __forceinline__ uint2 pack4(float a, float b, float c, float d) {
    __nv_bfloat162 lo = __floats2bfloat162_rn(a, b);
    __nv_bfloat162 hi = __floats2bfloat162_rn(c, d);
    uint2 r;
    r.x = *reinterpret_cast<u32*>(&lo);
    r.y = *reinterpret_cast<u32*>(&hi);
    return r;
}

// ---------------------------------------------------------------------------
// Kernel 1: gather+mean, hi/lo bf16 split of x and xn; weight pack (blocks<512);
// block 0 zeroes BN stat accumulators.
// ---------------------------------------------------------------------------
__global__ __launch_bounds__(256) void k_gather(const float4* __restrict__ x4,
                                                const int* __restrict__ idx,
                                                const float* __restrict__ Wx,
                                                const float* __restrict__ Wn) {
    const int tid = threadIdx.x;
    if (blockIdx.x == 0) {
        g_sum[tid] = 0.f;   g_sum[tid + 256] = 0.f;
        g_sumsq[tid] = 0.f; g_sumsq[tid + 256] = 0.f;
    }
    if (blockIdx.x < Cq) {    // weight pack: channel = blockIdx, k = tid
        const int c = blockIdx.x;
        float wv = (c < 256) ? Wx[c * Fq + tid] : Wn[(c - 256) * Fq + tid];
        __nv_bfloat16 h = __float2bfloat16(wv);
        g_bh[c * Fq + tid] = h;
        g_bl[c * Fq + tid] = __float2bfloat16(wv - __bfloat162float(h));
    }
    __shared__ int nbr[4][Kq];
    const int rr = tid >> 6;
    const int q  = tid & 63;
    const int r  = blockIdx.x * 4 + rr;
    const int b  = r >> 11;
    const int n  = r & (Nq - 1);

    if (tid < 128) {
        int k   = tid & 31;
        int rr2 = tid >> 5;
        int n2  = (blockIdx.x * 4 + rr2) & (Nq - 1);
        nbr[rr2][k] = idx[n2 * Kq + k];
    }
    __syncthreads();

    const float4* xb = x4 + (size_t)b * Nq * (Fq / 4);
    float4 acc = make_float4(0.f, 0.f, 0.f, 0.f);
#pragma unroll
    for (int k = 0; k < Kq; k++) {
        float4 v = xb[(size_t)nbr[rr][k] * (Fq / 4) + q];
        acc.x += v.x; acc.y += v.y; acc.z += v.z; acc.w += v.w;
    }
    const float s = 1.f / 32.f;
    acc.x *= s; acc.y *= s; acc.z *= s; acc.w *= s;
    const float4 xv = xb[(size_t)n * (Fq / 4) + q];

    const size_t o = (size_t)r * Fq + 4 * q;
    float h0, h1, h2, h3;
    h0 = __bfloat162float(__float2bfloat16(xv.x));
    h1 = __bfloat162float(__float2bfloat16(xv.y));
    h2 = __bfloat162float(__float2bfloat16(xv.z));
    h3 = __bfloat162float(__float2bfloat16(xv.w));
    *(uint2*)(g_ah + o) = pack4(h0, h1, h2, h3);
    *(uint2*)(g_al + o) = pack4(xv.x - h0, xv.y - h1, xv.z - h2, xv.w - h3);
    h0 = __bfloat162float(__float2bfloat16(acc.x));
    h1 = __bfloat162float(__float2bfloat16(acc.y));
    h2 = __bfloat162float(__float2bfloat16(acc.z));
    h3 = __bfloat162float(__float2bfloat16(acc.w));
    *(uint2*)(g_anh + o) = pack4(h0, h1, h2, h3);
    *(uint2*)(g_anl + o) = pack4(acc.x - h0, acc.y - h1, acc.z - h2, acc.w - h3);
}

// ---------------------------------------------------------------------------
// Kernel 2: mma.sync bf16 dual GEMM, 3-term hi/lo fp32 emulation, fused
// bias / row L2-norm / ReLU / BN-stat epilogue.
// CTA: 64 rows x 512 channels, 256 threads (8 warps)  [R7 shape — reg-safe].
// Warp (wr = w>>2, wc = w&3): rows wr*32..+32, channels wc*128..+128.
// wc<2 -> A = x (self channels), wc>=2 -> A = xn (neighbor channels).
// K pipeline: 16 steps of k16, 3-stage 16B cp.async, ONE barrier per step.
// ---------------------------------------------------------------------------
#define APITCH 48                 // bytes per 16-bf16 row (32B data + pad)
#define AOFF  3072                // per A-array tile bytes (64*48)
#define BOFF  24576               // per B-array tile bytes (512*48)
#define STAGE_SZ (4*AOFF + 2*BOFF)   // 61440
#define NSTG 3
#define SM_TILES 4608             // tiles (and epi staging) start here
#define EPITCH 516                // epilogue staging pitch (floats)
#define SMEMM (SM_TILES + NSTG*STAGE_SZ)   // 188928

__global__ __launch_bounds__(256, 1) void k_mma(const float* __restrict__ bx,
                                                const float* __restrict__ bn,
                                                float* __restrict__ out) {
    extern __shared__ char sm[];
    float* sbias = (float*)sm;            // [512]
    float* ssqp  = (float*)(sm + 2048);   // [64][4]
    float* rinv  = (float*)(sm + 3072);   // [64]

    const int tid  = threadIdx.x;
    const int lane = tid & 31;
    const int w    = tid >> 5;
    const int wr   = w >> 2;              // row half
    const int wc   = w & 3;               // channel quarter
    const int row0 = blockIdx.x * 64;

    sbias[tid] = bx[tid];  sbias[tid + 256] = bn[tid];

    // ---- async tile loader (recompute each call — keeps registers free) ----
    auto issue = [&](int kt, int st) {
        const u32 sb = s2u(sm) + SM_TILES + st * STAGE_SZ;
        const int ko = kt * 16;
        // A: arrays {xh, xl, nh, nl}; 128 16B-chunks each; 2 per thread.
#pragma unroll
        for (int i = 0; i < 2; i++) {
            const int hiarr = tid >> 7;              // 0: hi, 1: lo
            const int arr   = i * 2 + hiarr;         // 0 xh,1 xl,2 nh,3 nl
            const int idx2  = tid & 127;
            const int r  = idx2 >> 1;
            const int hf = idx2 & 1;
            const __nv_bfloat16* gp =
                (i == 0) ? (hiarr ? g_al : g_ah) : (hiarr ? g_anl : g_anh);
            cp16(sb + arr * AOFF + r * APITCH + hf * 16,
                 gp + (size_t)(row0 + r) * Fq + ko + hf * 8);
        }
        // B: arrays {bh, bl}; 1024 chunks each; 8 per thread (arr = i>>2).
#pragma unroll
        for (int i = 0; i < 8; i++) {
            const int b2 = tid + 256 * i;
            const int arr = i >> 2;
            const int idx2 = b2 & 1023;
            const int c  = idx2 >> 1;
            const int hf = idx2 & 1;
            const __nv_bfloat16* gp = arr ? g_bl : g_bh;
            cp16(sb + 4 * AOFF + arr * BOFF + c * APITCH + hf * 16,
                 gp + (size_t)c * Fq + ko + hf * 8);
        }
        asm volatile("cp.async.commit_group;");
    };

    float acc[2][16][4];
#pragma unroll
    for (int mt = 0; mt < 2; mt++)
#pragma unroll
        for (int tn = 0; tn < 16; tn++)
#pragma unroll
            for (int k = 0; k < 4; k++) acc[mt][tn][k] = 0.f;

    issue(0, 0);
    issue(1, 1);

    const int arow   = (lane & 7) + ((lane >> 3) & 1) * 8;
    const int acol16 = (lane >> 4) * 16;
    const int brow   = lane & 7;
    const int bcol16 = ((lane >> 3) & 1) * 16;

    int st = 0;                 // kt % 3
    int stn = 2;                // (kt+2) % 3
    for (int kt = 0; kt < 16; kt++) {
        if (kt < 15) asm volatile("cp.async.wait_group 1;");
        else         asm volatile("cp.async.wait_group 0;");
        __syncthreads();

        if (kt < 14) issue(kt + 2, stn);   // overwrites stage (kt+2)%3 = (kt-1)%3: safe

        const u32 sb = s2u(sm) + SM_TILES + st * STAGE_SZ;
        const u32 ab = sb + ((wc >= 2) ? 2 * AOFF : 0);   // xh or nh
        const u32 bb = sb + 4 * AOFF;

        u32 ahi[2][4], alo[2][4];
#pragma unroll
        for (int mt = 0; mt < 2; mt++) {
            const u32 ad = ab + (wr * 32 + mt * 16 + arow) * APITCH + acol16;
            ldmx4(ahi[mt], ad);
            ldmx4(alo[mt], ad + AOFF);
        }
#pragma unroll
        for (int nc = 0; nc < 4; nc++) {
            u32 bhf[4][2], blf[4][2];
#pragma unroll
            for (int j = 0; j < 4; j++) {
                const int ch = wc * 128 + (nc * 4 + j) * 8;
                const u32 bd = bb + (ch + brow) * APITCH + bcol16;
                ldmx2(bhf[j], bd);
                ldmx2(blf[j], bd + BOFF);
            }
#pragma unroll
            for (int mt = 0; mt < 2; mt++)
#pragma unroll
                for (int j = 0; j < 4; j++) {
                    float* d = acc[mt][nc * 4 + j];
                    mma16816(d, ahi[mt], bhf[j]);
                    mma16816(d, ahi[mt], blf[j]);
                    mma16816(d, alo[mt], bhf[j]);
                }
        }

        st  = (st == 2)  ? 0 : st + 1;
        stn = (stn == 2) ? 0 : stn + 1;
    }
    __syncthreads();

    // ---- Epilogue: stage bias-added accums to smem [64][EPITCH] ----
    float* sg = (float*)(sm + SM_TILES);
#pragma unroll
    for (int mt = 0; mt < 2; mt++) {
        const int re = wr * 32 + mt * 16 + (lane >> 2);
#pragma unroll
        for (int tn = 0; tn < 16; tn++) {
            const int col = wc * 128 + tn * 8 + 2 * (lane & 3);
            const float2 bv = *(float2*)&sbias[col];
            float* p0 = &sg[re * EPITCH + col];
            p0[0] = acc[mt][tn][0] + bv.x;
            p0[1] = acc[mt][tn][1] + bv.y;
            float* p1 = &sg[(re + 8) * EPITCH + col];
            p1[0] = acc[mt][tn][2] + bv.x;
            p1[1] = acc[mt][tn][3] + bv.y;
        }
    }
    __syncthreads();

    // row sum-of-squares: thread -> (row = tid>>2, quarter = tid&3)
    {
        const int r = tid >> 2, q = tid & 3;
        const float4* rp = (const float4*)&sg[r * EPITCH + q * 128];
        float s = 0.f;
#pragma unroll
        for (int i = 0; i < 32; i++) {
            float4 v = rp[i];
            s += v.x * v.x + v.y * v.y + v.z * v.z + v.w * v.w;
        }
        ssqp[r * 4 + q] = s;
    }
    __syncthreads();
    if (tid < 64) {
        const float s = ssqp[tid * 4] + ssqp[tid * 4 + 1]
                      + ssqp[tid * 4 + 2] + ssqp[tid * 4 + 3];
        rinv[tid] = 1.f / fmaxf(sqrtf(s), 1e-12f);
    }
    __syncthreads();

    // normalize + relu + store + BN stats. thread: c4 = tid&127, rh = tid>>7.
    {
        const int c4 = tid & 127;
        const int rh = tid >> 7;
        float s0 = 0.f, s1 = 0.f, s2 = 0.f, s3 = 0.f;
        float q0 = 0.f, q1 = 0.f, q2 = 0.f, q3 = 0.f;
#pragma unroll 4
        for (int i = 0; i < 32; i++) {
            const int r = rh * 32 + i;
            float4 v = *(float4*)&sg[r * EPITCH + c4 * 4];
            const float rv = rinv[r];
            v.x = fmaxf(v.x * rv, 0.f); v.y = fmaxf(v.y * rv, 0.f);
            v.z = fmaxf(v.z * rv, 0.f); v.w = fmaxf(v.w * rv, 0.f);
            *(float4*)(out + (size_t)(row0 + r) * Cq + c4 * 4) = v;
            s0 += v.x; s1 += v.y; s2 += v.z; s3 += v.w;
            q0 += v.x * v.x; q1 += v.y * v.y; q2 += v.z * v.z; q3 += v.w * v.w;
        }
        atomicAdd(&g_sum[c4 * 4 + 0], s0);  atomicAdd(&g_sum[c4 * 4 + 1], s1);
        atomicAdd(&g_sum[c4 * 4 + 2], s2);  atomicAdd(&g_sum[c4 * 4 + 3], s3);
        atomicAdd(&g_sumsq[c4 * 4 + 0], q0); atomicAdd(&g_sumsq[c4 * 4 + 1], q1);
        atomicAdd(&g_sumsq[c4 * 4 + 2], q2); atomicAdd(&g_sumsq[c4 * 4 + 3], q3);
    }
}

// ---------------------------------------------------------------------------
// Kernel 3: per-block BN fold (stats -> scale/shift in smem) + apply, 4x ILP.
// ---------------------------------------------------------------------------
#define QUAR ((size_t)Mq * (Cq / 4) / 4)     // float4 count of quarter output
__global__ __launch_bounds__(256) void k_apply(float4* __restrict__ out4,
                                               const float* __restrict__ gamma,
                                               const float* __restrict__ beta) {
    __shared__ float sc[Cq], sh[Cq];
    const int t = threadIdx.x;
    const float inv_n = 1.f / (float)Mq;
#pragma unroll
    for (int o = 0; o < 2; o++) {
        const int c = t + 256 * o;
        float mu  = g_sum[c] * inv_n;
        float var = fmaxf(g_sumsq[c] * inv_n - mu * mu, 0.f);
        float iv  = rsqrtf(var + 1e-5f);
        float s   = gamma[c] * iv;
        sc[c] = s;
        sh[c] = beta[c] - mu * s;
    }
    __syncthreads();
    const size_t i = (size_t)blockIdx.x * 256 + t;
    const int p = (int)(i & 127) * 4;
    const float4 s4 = *(float4*)&sc[p];
    const float4 h4 = *(float4*)&sh[p];
#pragma unroll
    for (int u = 0; u < 4; u++) {
        float4 v = out4[i + u * QUAR];
        v.x = v.x * s4.x + h4.x;  v.y = v.y * s4.y + h4.y;
        v.z = v.z * s4.z + h4.z;  v.w = v.w * s4.w + h4.w;
        out4[i + u * QUAR] = v;
    }
}

// ---------------------------------------------------------------------------
extern "C" void kernel_launch(void* const* d_in, const int* in_sizes, int n_in,
                              void* d_out, int out_size) {
    const float* x     = (const float*)d_in[0];
    const int*   idx   = (const int*)  d_in[1];
    const float* Wx    = (const float*)d_in[2];
    const float* bx    = (const float*)d_in[3];
    const float* Wn    = (const float*)d_in[4];
    const float* bn    = (const float*)d_in[5];
    const float* gamma = (const float*)d_in[6];
    const float* beta  = (const float*)d_in[7];
    float* out = (float*)d_out;

    cudaFuncSetAttribute(k_mma, cudaFuncAttributeMaxDynamicSharedMemorySize,
                         SMEMM);

    k_gather<<<Mq / 4, 256>>>((const float4*)x, idx, Wx, Wn);
    k_mma<<<Mq / 64, 256, SMEMM>>>(bx, bn, out);
    k_apply<<<(int)(QUAR / 256), 256>>>((float4*)out, gamma, beta);
}